// round 2
// baseline (speedup 1.0000x reference)
#include <cuda_runtime.h>
#include <math.h>

#define D_MODEL   1024
#define HEADS     16
#define HEAD_DIM  64
#define BATCH     2
#define SEQ       2048
#define M_ROWS    (BATCH * SEQ)      // 4096
#define ATT_SCALE 0.125f             // 1/sqrt(64)

// Scratch: Q,K,V in [B,H,S,Hd] layout; AO in [B,S,D] layout. 16 MB each.
__device__ float g_Q [BATCH * HEADS * SEQ * HEAD_DIM];
__device__ float g_K [BATCH * HEADS * SEQ * HEAD_DIM];
__device__ float g_V [BATCH * HEADS * SEQ * HEAD_DIM];
__device__ float g_AO[M_ROWS * D_MODEL];

// ---------------------------------------------------------------------------
// GEMM: out[r][c] = sum_k A[r][k] * W[c][k] + bias[c]     (y = x @ W^T + b)
// A: [4096, 1024] row-major, W: [1024, 1024] row-major.
// mode 0: out row-major [4096, 1024]
// mode 1: out scattered into [B,H,S,Hd] (head-transposed) layout
// Tile 64x64, BK=16, 256 threads, 4x4 per-thread with strided micro-tiles.
// ---------------------------------------------------------------------------
__global__ __launch_bounds__(256) void gemm_bias_kernel(
    const float* __restrict__ A, const float* __restrict__ W,
    const float* __restrict__ bias, float* __restrict__ out, int mode)
{
    __shared__ float As[64 * 17];
    __shared__ float Bs[64 * 17];

    const int tid = threadIdx.x;
    const int tx  = tid & 15;
    const int ty  = tid >> 4;
    const int rowBase = blockIdx.y * 64;
    const int colBase = blockIdx.x * 64;

    // loader mapping: each thread loads one float4 of A-tile and one of B-tile
    const int lr = tid >> 2;          // 0..63
    const int lv = (tid & 3) << 2;    // 0,4,8,12

    const float* Aptr = A + (size_t)(rowBase + lr) * D_MODEL + lv;
    const float* Wptr = W + (size_t)(colBase + lr) * D_MODEL + lv;

    float acc[4][4];
    #pragma unroll
    for (int i = 0; i < 4; ++i)
        #pragma unroll
        for (int j = 0; j < 4; ++j) acc[i][j] = 0.0f;

    for (int k0 = 0; k0 < D_MODEL; k0 += 16) {
        float4 av = *(const float4*)(Aptr + k0);
        float4 wv = *(const float4*)(Wptr + k0);
        As[lr * 17 + lv + 0] = av.x;
        As[lr * 17 + lv + 1] = av.y;
        As[lr * 17 + lv + 2] = av.z;
        As[lr * 17 + lv + 3] = av.w;
        Bs[lr * 17 + lv + 0] = wv.x;
        Bs[lr * 17 + lv + 1] = wv.y;
        Bs[lr * 17 + lv + 2] = wv.z;
        Bs[lr * 17 + lv + 3] = wv.w;
        __syncthreads();

        #pragma unroll
        for (int k = 0; k < 16; ++k) {
            float a[4], b[4];
            #pragma unroll
            for (int i = 0; i < 4; ++i) a[i] = As[(ty + 16 * i) * 17 + k];
            #pragma unroll
            for (int j = 0; j < 4; ++j) b[j] = Bs[(tx + 16 * j) * 17 + k];
            #pragma unroll
            for (int i = 0; i < 4; ++i)
                #pragma unroll
                for (int j = 0; j < 4; ++j) acc[i][j] = fmaf(a[i], b[j], acc[i][j]);
        }
        __syncthreads();
    }

    #pragma unroll
    for (int i = 0; i < 4; ++i) {
        const int r = rowBase + ty + 16 * i;
        const int b = r >> 11;          // / SEQ
        const int s = r & (SEQ - 1);
        #pragma unroll
        for (int j = 0; j < 4; ++j) {
            const int c = colBase + tx + 16 * j;
            const float v = acc[i][j] + bias[c];
            if (mode == 0) {
                out[(size_t)r * D_MODEL + c] = v;
            } else {
                const int h  = c >> 6;
                const int dd = c & 63;
                out[(size_t)(((b << 4) | h) * SEQ + s) * HEAD_DIM + dd] = v;
            }
        }
    }
}

// ---------------------------------------------------------------------------
// Flash attention: one CTA handles 64 query rows of one (b,h).
// Q,K,V: [B*H, S, 64]. AO: [B, S, D] with head h at cols h*64..h*64+63.
// Online softmax, fp32. 256 threads, 4x4 register tiles (strided mapping).
// ---------------------------------------------------------------------------
#define FP_PAD 65
#define FLASH_SMEM (4 * 64 * FP_PAD * (int)sizeof(float))

__global__ __launch_bounds__(256) void flash_attn_kernel(
    const float* __restrict__ Q, const float* __restrict__ K,
    const float* __restrict__ V, float* __restrict__ AO)
{
    extern __shared__ float sm[];
    float* Qs = sm;                    // 64 x 65
    float* Ks = sm + 64 * FP_PAD;      // 64 x 65
    float* Vs = sm + 2 * 64 * FP_PAD;  // 64 x 65
    float* Ps = sm + 3 * 64 * FP_PAD;  // 64 x 65

    const int tid = threadIdx.x;
    const int tx  = tid & 15;
    const int ty  = tid >> 4;
    const int qb  = blockIdx.x;        // 0..31
    const int bh  = blockIdx.y;        // 0..31

    const int lr = tid >> 2;           // 0..63 (row)
    const int lv = (tid & 3) << 2;     // 0,4,8,12 (column chunk base)

    // Load Q tile: 64x64 floats -> each thread loads 4 float4s (cols lv+16c)
    {
        const float* Qg = Q + (size_t)(bh * SEQ + qb * 64) * HEAD_DIM + lr * HEAD_DIM;
        #pragma unroll
        for (int c = 0; c < 4; ++c) {
            const int col = lv + 16 * c;
            float4 qv = *(const float4*)(Qg + col);
            Qs[lr * FP_PAD + col + 0] = qv.x;
            Qs[lr * FP_PAD + col + 1] = qv.y;
            Qs[lr * FP_PAD + col + 2] = qv.z;
            Qs[lr * FP_PAD + col + 3] = qv.w;
        }
    }

    float m[4], l[4], o[4][4];
    #pragma unroll
    for (int i = 0; i < 4; ++i) {
        m[i] = -1e30f; l[i] = 0.0f;
        #pragma unroll
        for (int j = 0; j < 4; ++j) o[i][j] = 0.0f;
    }

    const float* Kg = K + (size_t)bh * SEQ * HEAD_DIM;
    const float* Vg = V + (size_t)bh * SEQ * HEAD_DIM;

    for (int kb = 0; kb < SEQ / 64; ++kb) {
        __syncthreads();   // previous iteration done with Ks/Vs/Ps; Qs visible (iter 0)

        {
            const float* Kr = Kg + (size_t)(kb * 64 + lr) * HEAD_DIM;
            const float* Vr = Vg + (size_t)(kb * 64 + lr) * HEAD_DIM;
            #pragma unroll
            for (int c = 0; c < 4; ++c) {
                const int col = lv + 16 * c;
                float4 kv4 = *(const float4*)(Kr + col);
                float4 vv4 = *(const float4*)(Vr + col);
                Ks[lr * FP_PAD + col + 0] = kv4.x;
                Ks[lr * FP_PAD + col + 1] = kv4.y;
                Ks[lr * FP_PAD + col + 2] = kv4.z;
                Ks[lr * FP_PAD + col + 3] = kv4.w;
                Vs[lr * FP_PAD + col + 0] = vv4.x;
                Vs[lr * FP_PAD + col + 1] = vv4.y;
                Vs[lr * FP_PAD + col + 2] = vv4.z;
                Vs[lr * FP_PAD + col + 3] = vv4.w;
            }
        }
        __syncthreads();

        // S = (Q K^T) * scale
        float s[4][4];
        #pragma unroll
        for (int i = 0; i < 4; ++i)
            #pragma unroll
            for (int j = 0; j < 4; ++j) s[i][j] = 0.0f;

        #pragma unroll 8
        for (int k = 0; k < HEAD_DIM; ++k) {
            float a[4], b[4];
            #pragma unroll
            for (int i = 0; i < 4; ++i) a[i] = Qs[(ty + 16 * i) * FP_PAD + k];
            #pragma unroll
            for (int j = 0; j < 4; ++j) b[j] = Ks[(tx + 16 * j) * FP_PAD + k];
            #pragma unroll
            for (int i = 0; i < 4; ++i)
                #pragma unroll
                for (int j = 0; j < 4; ++j) s[i][j] = fmaf(a[i], b[j], s[i][j]);
        }

        // online softmax update (row reductions over the 16-lane half-warp group)
        #pragma unroll
        for (int i = 0; i < 4; ++i) {
            #pragma unroll
            for (int j = 0; j < 4; ++j) s[i][j] *= ATT_SCALE;

            float mt = fmaxf(fmaxf(s[i][0], s[i][1]), fmaxf(s[i][2], s[i][3]));
            #pragma unroll
            for (int off = 1; off < 16; off <<= 1)
                mt = fmaxf(mt, __shfl_xor_sync(0xffffffffu, mt, off));

            const float mn = fmaxf(m[i], mt);
            const float alpha = __expf(m[i] - mn);
            m[i] = mn;

            float rs = 0.0f;
            #pragma unroll
            for (int j = 0; j < 4; ++j) {
                const float p = __expf(s[i][j] - mn);
                Ps[(ty + 16 * i) * FP_PAD + tx + 16 * j] = p;
                rs += p;
            }
            #pragma unroll
            for (int off = 1; off < 16; off <<= 1)
                rs += __shfl_xor_sync(0xffffffffu, rs, off);

            l[i] = l[i] * alpha + rs;
            #pragma unroll
            for (int j = 0; j < 4; ++j) o[i][j] *= alpha;
        }
        __syncthreads();   // Ps visible to all

        // O += P @ V
        #pragma unroll 8
        for (int k = 0; k < 64; ++k) {
            float p[4], v[4];
            #pragma unroll
            for (int i = 0; i < 4; ++i) p[i] = Ps[(ty + 16 * i) * FP_PAD + k];
            #pragma unroll
            for (int j = 0; j < 4; ++j) v[j] = Vs[k * FP_PAD + tx + 16 * j];
            #pragma unroll
            for (int i = 0; i < 4; ++i)
                #pragma unroll
                for (int j = 0; j < 4; ++j) o[i][j] = fmaf(p[i], v[j], o[i][j]);
        }
    }

    // epilogue: normalize and scatter into [B,S,D]
    const int b = bh >> 4;
    const int h = bh & 15;
    #pragma unroll
    for (int i = 0; i < 4; ++i) {
        const int r   = qb * 64 + ty + 16 * i;
        const float inv = 1.0f / l[i];
        #pragma unroll
        for (int j = 0; j < 4; ++j) {
            const int c = tx + 16 * j;
            AO[(size_t)(b * SEQ + r) * D_MODEL + h * HEAD_DIM + c] = o[i][j] * inv;
        }
    }
}

// ---------------------------------------------------------------------------
extern "C" void kernel_launch(void* const* d_in, const int* in_sizes, int n_in,
                              void* d_out, int out_size)
{
    const float* Z  = (const float*)d_in[0];
    const float* Wq = (const float*)d_in[1];
    const float* bq = (const float*)d_in[2];
    const float* Wk = (const float*)d_in[3];
    const float* bk = (const float*)d_in[4];
    const float* Wv = (const float*)d_in[5];
    const float* bv = (const float*)d_in[6];
    const float* Wo = (const float*)d_in[7];
    const float* bo = (const float*)d_in[8];

    float *Qp, *Kp, *Vp, *AOp;
    cudaGetSymbolAddress((void**)&Qp,  g_Q);
    cudaGetSymbolAddress((void**)&Kp,  g_K);
    cudaGetSymbolAddress((void**)&Vp,  g_V);
    cudaGetSymbolAddress((void**)&AOp, g_AO);

    cudaFuncSetAttribute(flash_attn_kernel,
                         cudaFuncAttributeMaxDynamicSharedMemorySize, FLASH_SMEM);

    const dim3 ggrid(D_MODEL / 64, M_ROWS / 64);   // (16, 64)
    gemm_bias_kernel<<<ggrid, 256>>>(Z, Wq, bq, Qp, 1);
    gemm_bias_kernel<<<ggrid, 256>>>(Z, Wk, bk, Kp, 1);
    gemm_bias_kernel<<<ggrid, 256>>>(Z, Wv, bv, Vp, 1);

    flash_attn_kernel<<<dim3(SEQ / 64, BATCH * HEADS), 256, FLASH_SMEM>>>(Qp, Kp, Vp, AOp);

    gemm_bias_kernel<<<ggrid, 256>>>(AOp, Wo, bo, (float*)d_out, 0);
}